// round 5
// baseline (speedup 1.0000x reference)
#include <cuda_runtime.h>
#include <cuda_fp16.h>
#include <cstdint>
#include <cstddef>

// ============================================================================
// BitLinear: y = (x @ round(W/(mean|W|+eps))^T) * mean|W|
// x: (8192, 4096) fp32   W: (4096, 4096) fp32   y: (8192, 4096) fp32
//
// Wq = round(W/scale) is small-integer => exact in fp16. x -> fp16 (rel err
// ~2.8e-4 < 1e-3 threshold; measured 2.1e-4 in R4). Single fp16 mma.sync
// GEMM (M=8192, N=4096, K=4096), fp32 accum, epilogue * scale.
// R5: warp tile 32x128 -> 64x64 (square) to cut LDSM smem traffic 20%
// (MAC per smem byte 12.8 -> 16); mainloop modeled smem-read-bound.
// ============================================================================

#define EPSV 1e-5f

#define M_TOTAL 8192
#define N_TOTAL 4096
#define K_TOTAL 4096

#define BM 128
#define BN 256
#define BK 64
#define NUM_KT (K_TOTAL / BK)     // 64
#define STAGES 4
#define A_BYTES (BM * BK * 2)     // 16384
#define B_BYTES (BN * BK * 2)     // 32768
#define STAGE_BYTES (A_BYTES + B_BYTES)   // 49152
#define SMEM_DYN (STAGES * STAGE_BYTES)   // 196608

// ---------------------------------------------------------------------------
// Scratch (static device globals -- no allocation anywhere)
// ---------------------------------------------------------------------------
__device__ __align__(1024) __half g_xh[(size_t)M_TOTAL * K_TOTAL];  // 64 MB
__device__ __align__(1024) __half g_Wq[(size_t)N_TOTAL * K_TOTAL];  // 32 MB
__device__ float g_partials[4096];
__device__ float g_scale[2];   // [0] = scale, [1] = 1/(scale+eps)

// ---------------------------------------------------------------------------
// Helpers
// ---------------------------------------------------------------------------
__device__ __forceinline__ uint32_t smem_u32(const void* p) {
    uint32_t a;
    asm("{ .reg .u64 t; cvta.to.shared.u64 t, %1; cvt.u32.u64 %0, t; }" : "=r"(a) : "l"(p));
    return a;
}

__device__ __forceinline__ void cp_async16(uint32_t saddr, const void* gaddr) {
    asm volatile("cp.async.cg.shared.global [%0], [%1], 16;" :: "r"(saddr), "l"(gaddr) : "memory");
}
__device__ __forceinline__ void cp_commit() {
    asm volatile("cp.async.commit_group;" ::: "memory");
}
__device__ __forceinline__ void cp_wait2() {
    asm volatile("cp.async.wait_group 2;" ::: "memory");
}

__device__ __forceinline__ void ldsm_x4(uint32_t* r, uint32_t addr) {
    asm volatile("ldmatrix.sync.aligned.m8n8.x4.shared.b16 {%0,%1,%2,%3}, [%4];"
                 : "=r"(r[0]), "=r"(r[1]), "=r"(r[2]), "=r"(r[3]) : "r"(addr));
}

#define MMA_F16(d, a, b0, b1)                                                   \
    asm volatile(                                                               \
        "mma.sync.aligned.m16n8k16.row.col.f32.f16.f16.f32 "                    \
        "{%0,%1,%2,%3}, {%4,%5,%6,%7}, {%8,%9}, {%0,%1,%2,%3};"                 \
        : "+f"((d)[0]), "+f"((d)[1]), "+f"((d)[2]), "+f"((d)[3])                \
        : "r"((a)[0]), "r"((a)[1]), "r"((a)[2]), "r"((a)[3]), "r"(b0), "r"(b1))

// ---------------------------------------------------------------------------
// Prep kernels
// ---------------------------------------------------------------------------
__global__ void absum_partial_kernel(const float* __restrict__ W) {
    __shared__ float sh[256];
    const float* p = W + (size_t)blockIdx.x * 4096;
    float s = 0.0f;
    for (int i = threadIdx.x; i < 4096; i += 256) s += fabsf(p[i]);
    sh[threadIdx.x] = s;
    __syncthreads();
    for (int o = 128; o > 0; o >>= 1) {
        if (threadIdx.x < o) sh[threadIdx.x] += sh[threadIdx.x + o];
        __syncthreads();
    }
    if (threadIdx.x == 0) g_partials[blockIdx.x] = sh[0];
}

__global__ void absum_final_kernel() {
    __shared__ float sh[256];
    float s = 0.0f;
    for (int i = threadIdx.x; i < 4096; i += 256) s += g_partials[i];
    sh[threadIdx.x] = s;
    __syncthreads();
    for (int o = 128; o > 0; o >>= 1) {
        if (threadIdx.x < o) sh[threadIdx.x] += sh[threadIdx.x + o];
        __syncthreads();
    }
    if (threadIdx.x == 0) {
        float sc = sh[0] / 16777216.0f;          // mean |W|
        g_scale[0] = sc;
        g_scale[1] = 1.0f / (sc + EPSV);
    }
}

// Wq = fp16(rint(W * inv))  (exact: small integers)
__global__ void quant_kernel(const float* __restrict__ W) {
    int i = blockIdx.x * blockDim.x + threadIdx.x;   // one float4 per thread
    const float inv = g_scale[1];
    float4 v = reinterpret_cast<const float4*>(W)[i];
    __half2 p0, p1;
    p0.x = __float2half_rn(rintf(v.x * inv));
    p0.y = __float2half_rn(rintf(v.y * inv));
    p1.x = __float2half_rn(rintf(v.z * inv));
    p1.y = __float2half_rn(rintf(v.w * inv));
    __half2* dst = reinterpret_cast<__half2*>(g_Wq) + i * 2;
    dst[0] = p0;
    dst[1] = p1;
}

// x -> fp16
__global__ void convert_kernel(const float* __restrict__ x) {
    int i = blockIdx.x * blockDim.x + threadIdx.x;   // one float4 per thread
    float4 v = reinterpret_cast<const float4*>(x)[i];
    __half2 h0, h1;
    h0.x = __float2half_rn(v.x);
    h0.y = __float2half_rn(v.y);
    h1.x = __float2half_rn(v.z);
    h1.y = __float2half_rn(v.w);
    __half2* dst = reinterpret_cast<__half2*>(g_xh) + i * 2;
    dst[0] = h0;
    dst[1] = h1;
}

// ---------------------------------------------------------------------------
// GEMM: 128x256x64 tile, 4-stage cp.async pipeline, mma.sync m16n8k16 fp16.
// 256 threads = 8 warps, warp grid 2(M) x 4(N), warp tile 64x64 (square ->
// max MAC per smem byte). Smem rows: 64 fp16 = 128B; XOR swizzle
// chunk' = chunk ^ (row & 7).
// ---------------------------------------------------------------------------
__global__ void __launch_bounds__(256, 1) bitlinear_gemm(float* __restrict__ out) {
    extern __shared__ char smem[];
    const uint32_t s_base = smem_u32(smem);

    const int tid  = threadIdx.x;
    const int wid  = tid >> 5;
    const int lane = tid & 31;
    const int warpM = wid & 1;      // 0..1  (64 rows each)
    const int warpN = wid >> 1;     // 0..3  (64 cols each)

    // ---- cp.async base addressing.
    // Thread tid handles rows {r0 + 32*j}, fixed 16B chunk c0.
    // Swizzle offset invariant under +32 rows (32 % 8 == 0).
    const int r0 = tid >> 3;             // 0..31
    const int c0 = tid & 7;              // 0..7
    const uint32_t soff0 = (uint32_t)r0 * 128 + (uint32_t)((c0 ^ (r0 & 7)) << 4);
    const __half* a_gbase = g_xh + ((size_t)blockIdx.y * BM + r0) * K_TOTAL + c0 * 8;
    const __half* b_gbase = g_Wq + ((size_t)blockIdx.x * BN + r0) * K_TOTAL + c0 * 8;

    // ---- ldmatrix lane addressing
    const int sub = lane >> 3;          // 0..3
    const int lr  = lane & 7;
    const int a_row   = warpM * 64 + ((sub & 1) << 3) + lr;   // + mi*16
    const int a_k8sel = sub >> 1;
    const int a_row7  = a_row & 7;
    const int b_row   = warpN * 64 + ((sub >> 1) << 3) + lr;  // + g*16
    const int b_k8sel = sub & 1;
    const int b_row7  = b_row & 7;

    float c[4][8][4];
    #pragma unroll
    for (int mi = 0; mi < 4; mi++)
        #pragma unroll
        for (int t = 0; t < 8; t++)
            #pragma unroll
            for (int q = 0; q < 4; q++) c[mi][t][q] = 0.0f;

    // ---- prologue: stages 0..2
    #pragma unroll
    for (int s = 0; s < STAGES - 1; s++) {
        const uint32_t sb = s_base + s * STAGE_BYTES;
        #pragma unroll
        for (int j = 0; j < 4; j++)
            cp_async16(sb + soff0 + j * 4096, a_gbase + (size_t)(32 * j) * K_TOTAL + s * BK);
        #pragma unroll
        for (int j = 0; j < 8; j++)
            cp_async16(sb + A_BYTES + soff0 + j * 4096, b_gbase + (size_t)(32 * j) * K_TOTAL + s * BK);
        cp_commit();
    }

    // ---- mainloop
    for (int kt = 0; kt < NUM_KT; kt++) {
        cp_wait2();
        __syncthreads();

        // prefetch stage kt+3
        {
            int f = kt + STAGES - 1;
            if (f < NUM_KT) {
                const uint32_t sb = s_base + (f & (STAGES - 1)) * STAGE_BYTES;
                #pragma unroll
                for (int j = 0; j < 4; j++)
                    cp_async16(sb + soff0 + j * 4096, a_gbase + (size_t)(32 * j) * K_TOTAL + f * BK);
                #pragma unroll
                for (int j = 0; j < 8; j++)
                    cp_async16(sb + A_BYTES + soff0 + j * 4096, b_gbase + (size_t)(32 * j) * K_TOTAL + f * BK);
            }
            cp_commit();   // empty group when f >= NUM_KT keeps accounting uniform
        }

        const uint32_t aB = s_base + (kt & (STAGES - 1)) * STAGE_BYTES;
        const uint32_t bB = aB + A_BYTES;

        #pragma unroll
        for (int ks = 0; ks < 4; ks++) {
            uint32_t a[4][4];
            #pragma unroll
            for (int mi = 0; mi < 4; mi++) {
                uint32_t addr = aB + (uint32_t)(a_row + mi * 16) * 128
                              + (uint32_t)(((2 * ks + a_k8sel) ^ a_row7) << 4);
                ldsm_x4(a[mi], addr);
            }
            uint32_t b[4][4];
            #pragma unroll
            for (int g = 0; g < 4; g++) {
                uint32_t addr = bB + (uint32_t)(b_row + g * 16) * 128
                              + (uint32_t)(((2 * ks + b_k8sel) ^ b_row7) << 4);
                ldsm_x4(b[g], addr);
            }
            #pragma unroll
            for (int mi = 0; mi < 4; mi++)
                #pragma unroll
                for (int t = 0; t < 8; t++)
                    MMA_F16(c[mi][t], a[mi], b[t >> 1][(t & 1) * 2], b[t >> 1][(t & 1) * 2 + 1]);
        }
    }

    // ---- epilogue: * scale, coalesced float2 stores
    const float scale = g_scale[0];
    const int row0 = blockIdx.y * BM + warpM * 64 + (lane >> 2);
    const int col0 = blockIdx.x * BN + warpN * 64 + (lane & 3) * 2;
    #pragma unroll
    for (int mi = 0; mi < 4; mi++) {
        #pragma unroll
        for (int t = 0; t < 8; t++) {
            float2 v0 = make_float2(c[mi][t][0] * scale, c[mi][t][1] * scale);
            float2 v1 = make_float2(c[mi][t][2] * scale, c[mi][t][3] * scale);
            *reinterpret_cast<float2*>(out + (size_t)(row0 + mi * 16)     * N_TOTAL + col0 + t * 8) = v0;
            *reinterpret_cast<float2*>(out + (size_t)(row0 + mi * 16 + 8) * N_TOTAL + col0 + t * 8) = v1;
        }
    }
}

// ---------------------------------------------------------------------------
// Host launch
// ---------------------------------------------------------------------------
extern "C" void kernel_launch(void* const* d_in, const int* in_sizes, int n_in,
                              void* d_out, int out_size)
{
    const float* x = (const float*)d_in[0];
    const float* W = (const float*)d_in[1];
    float* out = (float*)d_out;

    // 1) scale = mean|W| (deterministic 2-pass reduction)
    absum_partial_kernel<<<4096, 256>>>(W);
    absum_final_kernel<<<1, 256>>>();

    // 2) quantize W -> fp16 Wq;  3) convert x -> fp16
    quant_kernel<<<(K_TOTAL * N_TOTAL / 4) / 256, 256>>>(W);
    convert_kernel<<<(int)(((size_t)M_TOTAL * K_TOTAL / 4) / 256), 256>>>(x);

    // 4) GEMM
    static bool attr_set = false;
    if (!attr_set) {
        cudaFuncSetAttribute(bitlinear_gemm,
                             cudaFuncAttributeMaxDynamicSharedMemorySize, SMEM_DYN);
        attr_set = true;
    }
    dim3 grid(N_TOTAL / BN, M_TOTAL / BM);   // (16, 64)
    bitlinear_gemm<<<grid, 256, SMEM_DYN>>>(out);
}